// round 5
// baseline (speedup 1.0000x reference)
#include <cuda_runtime.h>
#include <cstddef>
#include <cstdint>

#define U2   (512*512)
#define NBLK 128
#define NTHR 256
#define APAD 36
#define SMTILE (64*APAD + 32*APAD)   // A tile + B tile (floats)

// ---------------- device state (static, no allocation) ----------------
__device__ float g_H[2][3][U2];        // ping-pong hidden states
__device__ float g_W1[608*512];        // [WA0 ; WB0]
__device__ float g_W2[1024*512];       // [WA1 ; M01]
__device__ float g_W3[1024*512];       // [WA2 ; M12]
__device__ float g_Mo[512*32];         // WC2 @ Wout
__device__ float g_acc[512*32];        // running accumulator (mirror of regs)
__device__ float g_c0[512], g_c1[512], g_c2[512], g_co[32];
__device__ unsigned g_bar_cnt, g_bar_gen;

// ---------------- async copy helpers ----------------
__device__ __forceinline__ void cp16(float* dst_smem, const float* src) {
    unsigned d = (unsigned)__cvta_generic_to_shared(dst_smem);
    asm volatile("cp.async.cg.shared.global [%0], [%1], 16;" :: "r"(d), "l"(src));
}
__device__ __forceinline__ void cp_commit() { asm volatile("cp.async.commit_group;"); }
template<int N> __device__ __forceinline__ void cp_wait() {
    asm volatile("cp.async.wait_group %0;" :: "n"(N));
}

// ---------------- grid barrier (128 co-resident CTAs) ----------------
__device__ __forceinline__ void grid_sync() {
    __syncthreads();
    if (threadIdx.x == 0) {
        __threadfence();
        volatile unsigned* vgen = &g_bar_gen;
        unsigned gen = *vgen;
        if (atomicAdd(&g_bar_cnt, 1u) == NBLK - 1u) {
            g_bar_cnt = 0;
            __threadfence();
            *vgen = gen + 1u;
        } else {
            while (*vgen == gen) { }
        }
        __threadfence();
    }
    __syncthreads();
}

// ---------------- one GEMM stage inside the persistent kernel ----------------
// C[512x512] = concat-A @ B + bias. A sources along K (tile-aligned):
//   kt <  e0 -> A0 (stride s0) ; e0 <= kt < e1 -> A1 (stride s1) ; else A2 (s2)
__device__ __forceinline__ void do_stage(
    const float* __restrict__ A0, int s0, int e0,
    const float* __restrict__ A1, int s1,
    const float* __restrict__ A2, int s2, int e1,
    const float* __restrict__ Bm, const float* __restrict__ bias,
    float* __restrict__ Cc, int nKt,
    float (*sm)[SMTILE],
    int row0, int col0, int rg4, int cg2, int tid)
{
    const int ar  = tid >> 3;        // 0..31
    const int ak4 = (tid & 7) * 4;   // 0,4,...,28

    float acc[4][2] = {{0.f,0.f},{0.f,0.f},{0.f,0.f},{0.f,0.f}};

    auto issue = [&](int kt, int buf) {
        const float* Ap; int st; int off;
        if (kt < e0)      { Ap = A0; st = s0; off = 0; }
        else if (kt < e1) { Ap = A1; st = s1; off = e0 * 32; }
        else              { Ap = A2; st = s2; off = e1 * 32; }
        const int kloc = kt * 32 - off;
        float* As = sm[buf];
        float* Bs = sm[buf] + 64 * APAD;
        cp16(As + ar*APAD + ak4,        Ap + (size_t)(row0 + ar)      * st + kloc + ak4);
        cp16(As + (ar+32)*APAD + ak4,   Ap + (size_t)(row0 + ar + 32) * st + kloc + ak4);
        cp16(Bs + ar*APAD + ak4,        Bm + (size_t)(kt*32 + ar) * 512 + col0 + ak4);
        cp_commit();
    };

    issue(0, 0);
    for (int kt = 0; kt < nKt; kt++) {
        if (kt + 1 < nKt) { issue(kt + 1, (kt + 1) & 1); cp_wait<1>(); }
        else              { cp_wait<0>(); }
        __syncthreads();
        const float* As = sm[kt & 1];
        const float* Bs = As + 64 * APAD;
        #pragma unroll
        for (int k = 0; k < 32; k += 2) {
            float2 b0 = *(const float2*)(Bs + k*APAD + cg2);
            float2 b1 = *(const float2*)(Bs + (k+1)*APAD + cg2);
            #pragma unroll
            for (int r = 0; r < 4; r++) {
                float2 a = *(const float2*)(As + (rg4 + r)*APAD + k);
                acc[r][0] = fmaf(a.x, b0.x, acc[r][0]);
                acc[r][1] = fmaf(a.x, b0.y, acc[r][1]);
                acc[r][0] = fmaf(a.y, b1.x, acc[r][0]);
                acc[r][1] = fmaf(a.y, b1.y, acc[r][1]);
            }
        }
        __syncthreads();
    }

    const float bb0 = bias[col0 + cg2];
    const float bb1 = bias[col0 + cg2 + 1];
    #pragma unroll
    for (int r = 0; r < 4; r++) {
        float2 v = make_float2(acc[r][0] + bb0, acc[r][1] + bb1);
        __stcg((float2*)(Cc + (size_t)(row0 + rg4 + r) * 512 + col0 + cg2), v);
    }
}

// ---------------- persistent time-loop kernel ----------------
__global__ void __launch_bounds__(NTHR, 1) rnn_persistent(
    const float* __restrict__ x, float* __restrict__ out)
{
    __shared__ float sm[2][SMTILE];
    const int tid = threadIdx.x;
    const int bid = blockIdx.x;

    // zero hidden states (ping buffer) + acc
    {
        float* h0 = &g_H[0][0][0];
        const int n = 3 * U2;
        for (int i = bid * NTHR + tid; i < n + 512*32; i += NBLK * NTHR) {
            if (i < n) h0[i] = 0.f; else g_acc[i - n] = 0.f;
        }
    }
    grid_sync();

    const int row0 = (bid >> 4) * 64;
    const int col0 = (bid & 15) * 32;
    const int rg4  = (tid >> 4) * 4;
    const int cg2  = (tid & 15) * 2;

    const int wid   = tid >> 5, lane = tid & 31;
    const int s4_b  = bid * 8 + wid;       // valid when bid < 64
    const int s4_cg = (lane & 7) * 4;
    const int s4_k0 = (lane >> 3) * 128;
    float4 accR = make_float4(0.f, 0.f, 0.f, 0.f);

    for (int t = 0; t < 512; t++) {
        const float* Hin  = &g_H[t & 1][0][0];
        float*       Hout = &g_H[(t & 1) ^ 1][0][0];

        // S1: H0' = [H0 | x_t | acc] @ W1 + c0   (19 k-tiles)
        do_stage(Hin, 512, 16,
                 x + (size_t)t * 64, 32768,
                 g_acc, 32, 18,
                 g_W1, g_c0, Hout, 19, sm, row0, col0, rg4, cg2, tid);
        grid_sync();
        // S2: H1' = [H1 | H0'] @ W2 + c1
        do_stage(Hin + U2, 512, 16, Hout, 512, Hout, 512, 32,
                 g_W2, g_c1, Hout + U2, 32, sm, row0, col0, rg4, cg2, tid);
        grid_sync();
        // S3: H2' = [H2 | H1'] @ W3 + c2
        do_stage(Hin + 2*U2, 512, 16, Hout + U2, 512, Hout, 512, 32,
                 g_W3, g_c2, Hout + 2*U2, 32, sm, row0, col0, rg4, cg2, tid);
        grid_sync();
        // S4: res = H2'@Mo + co ; out ; acc += res   (512 warps, k-quartered)
        if (bid < 64) {
            const float* H2 = Hout + 2*U2 + (size_t)s4_b * 512;
            float4 p = make_float4(0.f, 0.f, 0.f, 0.f);
            #pragma unroll 4
            for (int k = s4_k0; k < s4_k0 + 128; k += 4) {
                float4 hv = __ldcg((const float4*)(H2 + k));
                float4 m0 = __ldg((const float4*)(g_Mo + (size_t)(k+0)*32 + s4_cg));
                float4 m1 = __ldg((const float4*)(g_Mo + (size_t)(k+1)*32 + s4_cg));
                float4 m2 = __ldg((const float4*)(g_Mo + (size_t)(k+2)*32 + s4_cg));
                float4 m3 = __ldg((const float4*)(g_Mo + (size_t)(k+3)*32 + s4_cg));
                p.x += hv.x*m0.x + hv.y*m1.x + hv.z*m2.x + hv.w*m3.x;
                p.y += hv.x*m0.y + hv.y*m1.y + hv.z*m2.y + hv.w*m3.y;
                p.z += hv.x*m0.z + hv.y*m1.z + hv.z*m2.z + hv.w*m3.z;
                p.w += hv.x*m0.w + hv.y*m1.w + hv.z*m2.w + hv.w*m3.w;
            }
            #pragma unroll
            for (int m = 8; m <= 16; m <<= 1) {
                p.x += __shfl_xor_sync(0xffffffffu, p.x, m);
                p.y += __shfl_xor_sync(0xffffffffu, p.y, m);
                p.z += __shfl_xor_sync(0xffffffffu, p.z, m);
                p.w += __shfl_xor_sync(0xffffffffu, p.w, m);
            }
            float4 co4 = *(const float4*)(g_co + s4_cg);
            p.x += co4.x; p.y += co4.y; p.z += co4.z; p.w += co4.w;
            accR.x += p.x; accR.y += p.y; accR.z += p.z; accR.w += p.w;
            if (s4_k0 == 0) {
                *(float4*)(out + (size_t)s4_b * 16384 + (size_t)t * 32 + s4_cg) = p;
                __stcg((float4*)(g_acc + s4_b * 32 + s4_cg), accR);
            }
        }
        grid_sync();
    }
}

// ---------------- standalone GEMM for weight folding (runs once) ----------------
__global__ void __launch_bounds__(256) stage_gemm(
    const float* __restrict__ A0, int s0, int e0,
    const float* __restrict__ A1, int s1, int e1,
    const float* __restrict__ A2, int s2,
    const float* __restrict__ Bm, const float* __restrict__ bias,
    float* __restrict__ C, int nKt)
{
    __shared__ float As[64][33];
    __shared__ float Bs[32][33];
    const int tid  = threadIdx.x;
    const int row0 = (blockIdx.x >> 4) * 64;
    const int col0 = (blockIdx.x & 15) * 32;
    const int rg   = tid >> 4;
    const int cg   = tid & 15;
    float acc[4][2] = {};
    for (int kt = 0; kt < nKt; kt++) {
        const float* Ap; int st; int off;
        if (kt < e0)      { Ap = A0; st = s0; off = 0; }
        else if (kt < e1) { Ap = A1; st = s1; off = e0 * 32; }
        else              { Ap = A2; st = s2; off = e1 * 32; }
        const int kloc = kt * 32 - off;
        #pragma unroll
        for (int i = 0; i < 2; i++) {
            int e = tid + 256 * i; int r = e >> 3; int k4 = (e & 7) * 4;
            float4 v = *(const float4*)(Ap + (size_t)(row0 + r) * st + kloc + k4);
            As[r][k4+0]=v.x; As[r][k4+1]=v.y; As[r][k4+2]=v.z; As[r][k4+3]=v.w;
        }
        {
            int kr = tid >> 3; int c4 = (tid & 7) * 4;
            float4 v = *(const float4*)(Bm + (size_t)(kt*32 + kr) * 512 + col0 + c4);
            Bs[kr][c4+0]=v.x; Bs[kr][c4+1]=v.y; Bs[kr][c4+2]=v.z; Bs[kr][c4+3]=v.w;
        }
        __syncthreads();
        #pragma unroll
        for (int k = 0; k < 32; k++) {
            float b0 = Bs[k][cg*2], b1 = Bs[k][cg*2+1];
            #pragma unroll
            for (int r = 0; r < 4; r++) {
                float a = As[rg*4 + r][k];
                acc[r][0] += a * b0; acc[r][1] += a * b1;
            }
        }
        __syncthreads();
    }
    #pragma unroll
    for (int r = 0; r < 4; r++) {
        int row = row0 + rg*4 + r;
        #pragma unroll
        for (int j = 0; j < 2; j++) {
            int col = col0 + cg*2 + j;
            float b = bias ? bias[col] : 0.f;
            C[(size_t)row * 512 + col] = acc[r][j] + b;
        }
    }
}

__global__ void fold_mo(const float* __restrict__ WC2, const float* __restrict__ Wout) {
    int g = blockIdx.x * blockDim.x + threadIdx.x;  // 16384
    int k = g >> 5, p = g & 31;
    float s = 0.f;
    #pragma unroll 4
    for (int j = 0; j < 512; j++) s += WC2[(size_t)k*512 + j] * Wout[j*32 + p];
    g_Mo[k*32 + p] = s;
}

__global__ void bias_kernel(const float* __restrict__ bA,  const float* __restrict__ bB0,
                            const float* __restrict__ bBr, const float* __restrict__ bC,
                            const float* __restrict__ Wout,const float* __restrict__ bout,
                            const float* __restrict__ WBr) {
    int n = threadIdx.x;  // 512 threads
    g_c0[n] = bA[n] + bB0[n];
    float s1 = 0.f, s2 = 0.f;
    for (int k = 0; k < 512; k++) {
        s1 += bC[k]       * WBr[(size_t)k*512 + n];
        s2 += bC[512 + k] * WBr[(size_t)U2 + (size_t)k*512 + n];
    }
    g_c1[n] = bA[512 + n]  + bBr[n]       + s1;
    g_c2[n] = bA[1024 + n] + bBr[512 + n] + s2;
    if (n < 32) {
        float s = 0.f;
        for (int k = 0; k < 512; k++) s += bC[1024 + k] * Wout[k*32 + n];
        g_co[n] = bout[n] + s;
    }
}

// ---------------- host launch ----------------
extern "C" void kernel_launch(void* const* d_in, const int* in_sizes, int n_in,
                              void* d_out, int out_size)
{
    const float* x    = (const float*)d_in[0];
    const float* WA   = (const float*)d_in[1];
    const float* bA   = (const float*)d_in[2];
    const float* WB0  = (const float*)d_in[3];
    const float* bB0  = (const float*)d_in[4];
    const float* WBr  = (const float*)d_in[5];
    const float* bBr  = (const float*)d_in[6];
    const float* WC   = (const float*)d_in[7];
    const float* bC   = (const float*)d_in[8];
    const float* Wout = (const float*)d_in[9];
    const float* bout = (const float*)d_in[10];
    float* out = (float*)d_out;

    float *W1, *W2, *W3;
    cudaGetSymbolAddress((void**)&W1, g_W1);
    cudaGetSymbolAddress((void**)&W2, g_W2);
    cudaGetSymbolAddress((void**)&W3, g_W3);

    cudaMemcpyAsync(W1,      WA,          (size_t)U2 * 4,       cudaMemcpyDeviceToDevice);
    cudaMemcpyAsync(W1 + U2, WB0,         (size_t)96 * 512 * 4, cudaMemcpyDeviceToDevice);
    cudaMemcpyAsync(W2,      WA + U2,     (size_t)U2 * 4,       cudaMemcpyDeviceToDevice);
    cudaMemcpyAsync(W3,      WA + 2 * U2, (size_t)U2 * 4,       cudaMemcpyDeviceToDevice);
    // M01 = WC0 @ WBr0 ; M12 = WC1 @ WBr1
    stage_gemm<<<128, 256>>>(WC,      512, 16, WC, 512, 16, WC, 512,
                             WBr,      nullptr, W2 + U2, 16);
    stage_gemm<<<128, 256>>>(WC + U2, 512, 16, WC, 512, 16, WC, 512,
                             WBr + U2, nullptr, W3 + U2, 16);
    fold_mo<<<64, 256>>>(WC + 2 * U2, Wout);
    bias_kernel<<<1, 512>>>(bA, bB0, bBr, bC, Wout, bout, WBr);

    rnn_persistent<<<NBLK, NTHR>>>(x, out);
}